// round 15
// baseline (speedup 1.0000x reference)
#include <cuda_runtime.h>
#include <cuda_fp16.h>
#include <math.h>

#define D_HID   128
#define MAX_G   16384
#define MAX_N   65536
#define MAX_B   16384
#define SCAN_T  256
#define CAP     16

// Scratch (allocation-free rule: __device__ globals; zero-init at load)
__device__ __half g_H16[(size_t)MAX_N * D_HID];   // 16 MB fp16 copy of H
__device__ int    g_off[MAX_G + 1];
__device__ int    g_cnt[MAX_G];       // cleared by main_kernel per group
__device__ int    g_binfix[MAX_G * CAP];
__device__ int    g_worklist[MAX_G];
__device__ int    g_nwork;            // reset by main_kernel's last block
__device__ int    g_done;

// ---------------------------------------------------------------------------
// packed f32x2 helpers (SASS FFMA2 — PTX-only pattern)
// ---------------------------------------------------------------------------
__device__ __forceinline__ unsigned long long pack2(float lo, float hi) {
    unsigned long long r;
    asm("mov.b64 %0, {%1, %2};" : "=l"(r) : "f"(lo), "f"(hi));
    return r;
}
__device__ __forceinline__ void ffma2(unsigned long long& acc,
                                      unsigned long long a,
                                      unsigned long long b) {
    asm("fma.rn.f32x2 %0, %1, %2, %0;" : "+l"(acc) : "l"(a), "l"(b));
}
__device__ __forceinline__ float2 unpack2(unsigned long long v) {
    float2 f;
    asm("mov.b64 {%0, %1}, %2;" : "=f"(f.x), "=f"(f.y) : "l"(v));
    return f;
}

// ---------------------------------------------------------------------------
// Kernel 1 (prolog): convert H f32->fp16 | scan port_len -> g_off |
// hist+scatter pf_gid into bins + compact worklist of used groups.
// ---------------------------------------------------------------------------
__global__ void __launch_bounds__(SCAN_T)
prolog_kernel(const float4* __restrict__ H4, int n16,
              const int* __restrict__ plen,
              const int* __restrict__ pf_gid,
              float* __restrict__ out,
              int G, int B, int nconv, int nscan) {
    const int tid = threadIdx.x;

    if (blockIdx.x < nconv) {
        const int base = blockIdx.x * (SCAN_T * 4) + tid;
        #pragma unroll
        for (int k = 0; k < 4; k++) {
            const int i = base + k * SCAN_T;
            if (i < n16) {
                const float4 v0 = H4[2 * i];
                const float4 v1 = H4[2 * i + 1];
                __half2 a = __floats2half2_rn(v0.x, v0.y);
                __half2 b = __floats2half2_rn(v0.z, v0.w);
                __half2 cc = __floats2half2_rn(v1.x, v1.y);
                __half2 d = __floats2half2_rn(v1.z, v1.w);
                uint4 u;
                u.x = *reinterpret_cast<unsigned int*>(&a);
                u.y = *reinterpret_cast<unsigned int*>(&b);
                u.z = *reinterpret_cast<unsigned int*>(&cc);
                u.w = *reinterpret_cast<unsigned int*>(&d);
                reinterpret_cast<uint4*>(g_H16)[i] = u;
            }
        }
        return;
    }

    if (blockIdx.x < nconv + nscan) {
        const int blk = blockIdx.x - nconv;
        int pre = 0;
        const int lim = blk * SCAN_T;
        for (int i = tid; i < lim; i += SCAN_T) pre += plen[i];

        __shared__ int red[SCAN_T];
        red[tid] = pre;
        __syncthreads();
        for (int off = SCAN_T / 2; off > 0; off >>= 1) {
            if (tid < off) red[tid] += red[tid + off];
            __syncthreads();
        }
        const int base = red[0];
        __syncthreads();

        const int idx = lim + tid;
        const int v = (idx < G) ? plen[idx] : 0;
        __shared__ int sc[SCAN_T];
        sc[tid] = v;
        __syncthreads();
        for (int off = 1; off < SCAN_T; off <<= 1) {
            int t = (tid >= off) ? sc[tid - off] : 0;
            __syncthreads();
            sc[tid] += t;
            __syncthreads();
        }
        if (idx < G)      g_off[idx] = base + sc[tid] - v;
        if (idx == G - 1) g_off[G]   = base + sc[tid];
        return;
    }

    // ---- hist + scatter into fixed bins + compact worklist ----
    const int b = (blockIdx.x - nconv - nscan) * SCAN_T + tid;
    if (b < B) {
        const int g = pf_gid[b];
        if (g >= 0 && g < G) {
            const int slot = atomicAdd(&g_cnt[g], 1);
            if (slot < CAP) g_binfix[g * CAP + slot] = b;
            if (slot == 0) {
                const int p = atomicAdd(&g_nwork, 1);
                g_worklist[p] = g;
            }
        } else {
            float4* d0 = reinterpret_cast<float4*>(out + (size_t)b * D_HID);
            float4* d1 = reinterpret_cast<float4*>(out + (size_t)(B + b) * D_HID);
            const float4 z = make_float4(0.f, 0.f, 0.f, 0.f);
            for (int k = 0; k < D_HID / 4; k++) { d0[k] = z; d1[k] = z; }
        }
    }
}

// ---------------------------------------------------------------------------
// Kernel 2: main — one warp per worklist entry (dense: every warp works).
// Gather once (fp16, FFMA2); per-sample epilogues in-register.
// Last finishing block resets g_nwork / g_done for the next replay.
// ---------------------------------------------------------------------------
__global__ void __launch_bounds__(256, 5)
main_kernel(const float* __restrict__ H,
            const float* __restrict__ w,
            const int*   __restrict__ nodes,
            const int*   __restrict__ anchor_idx,
            const int*   __restrict__ pf_gid,
            float*       __restrict__ out,
            int B, int G) {
    const int nwork = g_nwork;
    const int wslot = threadIdx.x >> 5;
    const int widx  = blockIdx.x * 8 + wslot;

    __shared__ int2 sm[8][64];   // {node, signed w bits} (last tile kept)

    if (widx < nwork) {
        const int g   = g_worklist[widx];
        const int cnt = g_cnt[g];

        const int lane = threadIdx.x & 31;
        const int s    = lane >> 4;
        const int c    = lane & 15;

        const int start = g_off[g];
        const int end   = g_off[g + 1];
        const int len   = end - start;

        // ---- gather ----
        unsigned long long a0 = pack2(0.f, 0.f), a1 = a0, a2 = a0, a3 = a0;
        float wa = 0.f, ws = 0.f;

        for (int base = start; base < end; base += 64) {
            const int tcnt = min(64, end - base);
            if (2 * lane + 1 < tcnt) {
                const float2 w2 = *reinterpret_cast<const float2*>(w + base + 2 * lane);
                const int2   n2 = *reinterpret_cast<const int2*>(nodes + base + 2 * lane);
                ws += w2.x + w2.y;
                wa += fabsf(w2.x) + fabsf(w2.y);
                *reinterpret_cast<int4*>(&sm[wslot][2 * lane]) =
                    make_int4(n2.x, __float_as_int(w2.x), n2.y, __float_as_int(w2.y));
            } else if (2 * lane < tcnt) {
                const float ww = w[base + 2 * lane];
                const int   nd = nodes[base + 2 * lane];
                ws += ww; wa += fabsf(ww);
                sm[wslot][2 * lane] = make_int2(nd, __float_as_int(ww));
            }
            __syncwarp();

            if (tcnt == 64) {
                #pragma unroll 8
                for (int j = s; j < 64; j += 2) {
                    const int2 p = sm[wslot][j];
                    const float wwa = fabsf(__int_as_float(p.y));
                    const unsigned long long wp = pack2(wwa, wwa);
                    const uint4 u = *reinterpret_cast<const uint4*>(
                        g_H16 + (size_t)p.x * D_HID + c * 8);
                    const float2 f0 = __half22float2(*reinterpret_cast<const __half2*>(&u.x));
                    const float2 f1 = __half22float2(*reinterpret_cast<const __half2*>(&u.y));
                    const float2 f2 = __half22float2(*reinterpret_cast<const __half2*>(&u.z));
                    const float2 f3 = __half22float2(*reinterpret_cast<const __half2*>(&u.w));
                    ffma2(a0, pack2(f0.x, f0.y), wp);
                    ffma2(a1, pack2(f1.x, f1.y), wp);
                    ffma2(a2, pack2(f2.x, f2.y), wp);
                    ffma2(a3, pack2(f3.x, f3.y), wp);
                }
            } else {
                #pragma unroll 4
                for (int j = s; j < tcnt; j += 2) {
                    const int2 p = sm[wslot][j];
                    const float wwa = fabsf(__int_as_float(p.y));
                    const unsigned long long wp = pack2(wwa, wwa);
                    const uint4 u = *reinterpret_cast<const uint4*>(
                        g_H16 + (size_t)p.x * D_HID + c * 8);
                    const float2 f0 = __half22float2(*reinterpret_cast<const __half2*>(&u.x));
                    const float2 f1 = __half22float2(*reinterpret_cast<const __half2*>(&u.y));
                    const float2 f2 = __half22float2(*reinterpret_cast<const __half2*>(&u.z));
                    const float2 f3 = __half22float2(*reinterpret_cast<const __half2*>(&u.w));
                    ffma2(a0, pack2(f0.x, f0.y), wp);
                    ffma2(a1, pack2(f1.x, f1.y), wp);
                    ffma2(a2, pack2(f2.x, f2.y), wp);
                    ffma2(a3, pack2(f3.x, f3.y), wp);
                }
            }
            __syncwarp();
        }

        float acc[8];
        {
            const float2 r0 = unpack2(a0), r1 = unpack2(a1);
            const float2 r2 = unpack2(a2), r3 = unpack2(a3);
            acc[0] = r0.x; acc[1] = r0.y; acc[2] = r1.x; acc[3] = r1.y;
            acc[4] = r2.x; acc[5] = r2.y; acc[6] = r3.x; acc[7] = r3.y;
        }
        #pragma unroll
        for (int k = 0; k < 8; k++)
            acc[k] += __shfl_xor_sync(0xffffffff, acc[k], 16);
        #pragma unroll
        for (int o = 16; o > 0; o >>= 1) {
            wa += __shfl_xor_sync(0xffffffff, wa, o);
            ws += __shfl_xor_sync(0xffffffff, ws, o);
        }

        // ---- per-sample epilogue ----
        auto do_sample = [&](int b, int anchor) {
            // anchor row first (independent loads overlap the LOO scan)
            const float4* Ha4 = reinterpret_cast<const float4*>(H + (size_t)anchor * D_HID);
            const float4 h0 = Ha4[2 * c];
            const float4 h1 = Ha4[2 * c + 1];

            float swa = 0.f, sws = 0.f;
            if (len <= 64) {
                #pragma unroll
                for (int k = 0; k < 2; k++) {
                    const int j = lane + 32 * k;
                    if (j < len) {
                        const int2 p = sm[wslot][j];
                        if (p.x == anchor) {
                            const float ww = __int_as_float(p.y);
                            sws += ww; swa += fabsf(ww);
                        }
                    }
                }
            } else {
                for (int j = start + lane; j < end; j += 32) {
                    if (nodes[j] == anchor) {
                        const float ww = w[j];
                        sws += ww; swa += fabsf(ww);
                    }
                }
            }
            #pragma unroll
            for (int o = 16; o > 0; o >>= 1) {
                swa += __shfl_xor_sync(0xffffffff, swa, o);
                sws += __shfl_xor_sync(0xffffffff, sws, o);
            }

            const float ha[8] = { h0.x, h0.y, h0.z, h0.w, h1.x, h1.y, h1.z, h1.w };
            const float denom = fmaxf(wa - swa, 1e-12f);
            const float inv_d = 1.f / denom;
            const float sscale = (ws - sws) * inv_d;

            float v[8];
            float nv = 0.f;
            #pragma unroll
            for (int k = 0; k < 8; k++) {
                const float vk = (acc[k] - swa * ha[k]) * inv_d;
                v[k] = vk;
                nv += vk * vk;
            }
            #pragma unroll
            for (int o = 8; o > 0; o >>= 1)
                nv += __shfl_xor_sync(0xffffffff, nv, o);
            const float na = sqrtf(nv);
            const float ns = fabsf(sscale) * na;     // ||sscale * v|| exactly

            float o8[8];
            float* dst;
            if (s == 0) {
                const float inv = 1.f / fmaxf(na, 1e-6f);
                #pragma unroll
                for (int k = 0; k < 8; k++) o8[k] = v[k] * inv;
                dst = out + (size_t)b * D_HID + c * 8;
            } else {
                const float inv = (ns > 0.f) ? sscale / fmaxf(ns, 1e-6f) : sscale;
                #pragma unroll
                for (int k = 0; k < 8; k++) o8[k] = v[k] * inv;
                dst = out + (size_t)(B + b) * D_HID + c * 8;
            }
            reinterpret_cast<float4*>(dst)[0] = make_float4(o8[0], o8[1], o8[2], o8[3]);
            reinterpret_cast<float4*>(dst)[1] = make_float4(o8[4], o8[5], o8[6], o8[7]);
        };

        if (cnt <= CAP) {
            for (int i = 0; i < cnt; i++) {
                const int b = g_binfix[g * CAP + i];   // uniform L2-hit load
                do_sample(b, anchor_idx[b]);
            }
        } else {
            for (int base = 0; base < B; base += 32) {
                const int bb = base + lane;
                const bool m = (bb < B) && (pf_gid[bb] == g);
                unsigned mask = __ballot_sync(0xffffffff, m);
                while (mask) {
                    const int l = __ffs(mask) - 1;
                    mask &= mask - 1;
                    const int b = base + l;
                    do_sample(b, anchor_idx[b]);
                }
            }
        }

        if (lane == 0) g_cnt[g] = 0;   // clear hist for the next replay
    }

    // ---- block-exit protocol: last block resets the worklist counters ----
    __syncthreads();
    if (threadIdx.x == 0) {
        if (atomicAdd(&g_done, 1) == (int)gridDim.x - 1) {
            g_nwork = 0;
            g_done = 0;
        }
    }
}

// ---------------------------------------------------------------------------
extern "C" void kernel_launch(void* const* d_in, const int* in_sizes, int n_in,
                              void* d_out, int out_size) {
    const float* H      = (const float*)d_in[0];   // [N, 128]
    const float* w      = (const float*)d_in[1];   // [L]
    const int*   anchor = (const int*)  d_in[2];   // [B]
    const int*   pfgid  = (const int*)  d_in[3];   // [B]
    const int*   nodes  = (const int*)  d_in[4];   // [L]
    const int*   plen   = (const int*)  d_in[5];   // [G]
    float* out = (float*)d_out;                    // [2, B, 128]

    const int B = in_sizes[2];
    const int G = in_sizes[5];
    const int n16 = in_sizes[0] / 8;               // uint4 groups of fp16 out
    const int nconv = (n16 + SCAN_T * 4 - 1) / (SCAN_T * 4);
    const int nscan = (G + SCAN_T - 1) / SCAN_T;
    const int nhist = (B + SCAN_T - 1) / SCAN_T;

    prolog_kernel<<<nconv + nscan + nhist, SCAN_T>>>(
        (const float4*)H, n16, plen, pfgid, out, G, B, nconv, nscan);
    main_kernel<<<(G + 7) / 8, 256>>>(H, w, nodes, anchor, pfgid, out, B, G);
}

// round 16
// speedup vs baseline: 1.1173x; 1.1173x over previous
#include <cuda_runtime.h>
#include <cuda_fp16.h>
#include <math.h>

#define D_HID   128
#define MAX_G   16384
#define MAX_N   65536
#define MAX_B   16384
#define SCAN_T  256
#define CAP     16

// Scratch (allocation-free rule: __device__ globals; zero-init at load)
__device__ __half g_H16[(size_t)MAX_N * D_HID];   // 16 MB fp16 copy of H
__device__ int    g_off[MAX_G + 1];
__device__ int    g_cnt[MAX_G];       // cleared by clear_kernel each call
__device__ int    g_binfix[MAX_G * CAP];
__device__ int2   g_items[MAX_B];     // (group, even slot) work items
__device__ int    g_nwork;            // cleared by clear_kernel each call

// ---------------------------------------------------------------------------
// packed f32x2 helpers (SASS FFMA2 — PTX-only pattern)
// ---------------------------------------------------------------------------
__device__ __forceinline__ unsigned long long pack2(float lo, float hi) {
    unsigned long long r;
    asm("mov.b64 %0, {%1, %2};" : "=l"(r) : "f"(lo), "f"(hi));
    return r;
}
__device__ __forceinline__ void ffma2(unsigned long long& acc,
                                      unsigned long long a,
                                      unsigned long long b) {
    asm("fma.rn.f32x2 %0, %1, %2, %0;" : "+l"(acc) : "l"(a), "l"(b));
}
__device__ __forceinline__ float2 unpack2(unsigned long long v) {
    float2 f;
    asm("mov.b64 {%0, %1}, %2;" : "=f"(f.x), "=f"(f.y) : "l"(v));
    return f;
}

// ---------------------------------------------------------------------------
// Kernel 0: clear hist + work counter (runs before prolog each call).
// ---------------------------------------------------------------------------
__global__ void clear_kernel(int G) {
    const int i = blockIdx.x * blockDim.x + threadIdx.x;
    const int4 z = make_int4(0, 0, 0, 0);
    if (4 * i < G) reinterpret_cast<int4*>(g_cnt)[i] = z;
    if (i == 0) g_nwork = 0;
}

// ---------------------------------------------------------------------------
// Kernel 1 (prolog): convert H f32->fp16 | scan port_len -> g_off |
// hist+scatter pf_gid into bins + emit pair work items (even slots).
// ---------------------------------------------------------------------------
__global__ void __launch_bounds__(SCAN_T)
prolog_kernel(const float4* __restrict__ H4, int n16,
              const int* __restrict__ plen,
              const int* __restrict__ pf_gid,
              float* __restrict__ out,
              int G, int B, int nconv, int nscan) {
    const int tid = threadIdx.x;

    if (blockIdx.x < nconv) {
        const int base = blockIdx.x * (SCAN_T * 4) + tid;
        #pragma unroll
        for (int k = 0; k < 4; k++) {
            const int i = base + k * SCAN_T;
            if (i < n16) {
                const float4 v0 = H4[2 * i];
                const float4 v1 = H4[2 * i + 1];
                __half2 a = __floats2half2_rn(v0.x, v0.y);
                __half2 b = __floats2half2_rn(v0.z, v0.w);
                __half2 cc = __floats2half2_rn(v1.x, v1.y);
                __half2 d = __floats2half2_rn(v1.z, v1.w);
                uint4 u;
                u.x = *reinterpret_cast<unsigned int*>(&a);
                u.y = *reinterpret_cast<unsigned int*>(&b);
                u.z = *reinterpret_cast<unsigned int*>(&cc);
                u.w = *reinterpret_cast<unsigned int*>(&d);
                reinterpret_cast<uint4*>(g_H16)[i] = u;
            }
        }
        return;
    }

    if (blockIdx.x < nconv + nscan) {
        const int blk = blockIdx.x - nconv;
        int pre = 0;
        const int lim = blk * SCAN_T;
        for (int i = tid; i < lim; i += SCAN_T) pre += plen[i];

        __shared__ int red[SCAN_T];
        red[tid] = pre;
        __syncthreads();
        for (int off = SCAN_T / 2; off > 0; off >>= 1) {
            if (tid < off) red[tid] += red[tid + off];
            __syncthreads();
        }
        const int base = red[0];
        __syncthreads();

        const int idx = lim + tid;
        const int v = (idx < G) ? plen[idx] : 0;
        __shared__ int sc[SCAN_T];
        sc[tid] = v;
        __syncthreads();
        for (int off = 1; off < SCAN_T; off <<= 1) {
            int t = (tid >= off) ? sc[tid - off] : 0;
            __syncthreads();
            sc[tid] += t;
            __syncthreads();
        }
        if (idx < G)      g_off[idx] = base + sc[tid] - v;
        if (idx == G - 1) g_off[G]   = base + sc[tid];
        return;
    }

    // ---- hist + scatter into bins + emit pair items ----
    const int b = (blockIdx.x - nconv - nscan) * SCAN_T + tid;
    if (b < B) {
        const int g = pf_gid[b];
        if (g >= 0 && g < G) {
            const int slot = atomicAdd(&g_cnt[g], 1);
            if (slot < CAP) {
                g_binfix[g * CAP + slot] = b;
                if ((slot & 1) == 0) {
                    const int p = atomicAdd(&g_nwork, 1);
                    g_items[p] = make_int2(g, slot);
                }
            } else if (slot == CAP) {
                const int p = atomicAdd(&g_nwork, 1);
                g_items[p] = make_int2(g, CAP);   // overflow sentinel
            }
        } else {
            float4* d0 = reinterpret_cast<float4*>(out + (size_t)b * D_HID);
            float4* d1 = reinterpret_cast<float4*>(out + (size_t)(B + b) * D_HID);
            const float4 z = make_float4(0.f, 0.f, 0.f, 0.f);
            for (int k = 0; k < D_HID / 4; k++) { d0[k] = z; d1[k] = z; }
        }
    }
}

// ---------------------------------------------------------------------------
// Kernel 2: main — one warp per work item (pair of samples sharing a group).
// Gather once (fp16, FFMA2), then <=2 in-register epilogues. g_cnt is stable
// here (cleared only by clear_kernel), so reads are race-free.
// ---------------------------------------------------------------------------
__global__ void __launch_bounds__(256, 5)
main_kernel(const float* __restrict__ H,
            const float* __restrict__ w,
            const int*   __restrict__ nodes,
            const int*   __restrict__ anchor_idx,
            const int*   __restrict__ pf_gid,
            float*       __restrict__ out,
            int B, int G) {
    const int nwork = g_nwork;
    const int wslot = threadIdx.x >> 5;
    const int widx  = blockIdx.x * 8 + wslot;
    if (widx >= nwork) return;

    const int2 item = g_items[widx];
    const int g     = item.x;
    const int slot  = item.y;
    const int cnt   = g_cnt[g];

    const int lane = threadIdx.x & 31;
    const int s    = lane >> 4;
    const int c    = lane & 15;

    const int start = g_off[g];
    const int end   = g_off[g + 1];
    const int len   = end - start;

    __shared__ int2 sm[8][64];   // {node, signed w bits} (last tile kept)

    // ---- gather ----
    unsigned long long a0 = pack2(0.f, 0.f), a1 = a0, a2 = a0, a3 = a0;
    float wa = 0.f, ws = 0.f;

    for (int base = start; base < end; base += 64) {
        const int tcnt = min(64, end - base);
        if (2 * lane + 1 < tcnt) {
            const float2 w2 = *reinterpret_cast<const float2*>(w + base + 2 * lane);
            const int2   n2 = *reinterpret_cast<const int2*>(nodes + base + 2 * lane);
            ws += w2.x + w2.y;
            wa += fabsf(w2.x) + fabsf(w2.y);
            *reinterpret_cast<int4*>(&sm[wslot][2 * lane]) =
                make_int4(n2.x, __float_as_int(w2.x), n2.y, __float_as_int(w2.y));
        } else if (2 * lane < tcnt) {
            const float ww = w[base + 2 * lane];
            const int   nd = nodes[base + 2 * lane];
            ws += ww; wa += fabsf(ww);
            sm[wslot][2 * lane] = make_int2(nd, __float_as_int(ww));
        }
        __syncwarp();

        if (tcnt == 64) {
            #pragma unroll 8
            for (int j = s; j < 64; j += 2) {
                const int2 p = sm[wslot][j];
                const float wwa = fabsf(__int_as_float(p.y));
                const unsigned long long wp = pack2(wwa, wwa);
                const uint4 u = *reinterpret_cast<const uint4*>(
                    g_H16 + (size_t)p.x * D_HID + c * 8);
                const float2 f0 = __half22float2(*reinterpret_cast<const __half2*>(&u.x));
                const float2 f1 = __half22float2(*reinterpret_cast<const __half2*>(&u.y));
                const float2 f2 = __half22float2(*reinterpret_cast<const __half2*>(&u.z));
                const float2 f3 = __half22float2(*reinterpret_cast<const __half2*>(&u.w));
                ffma2(a0, pack2(f0.x, f0.y), wp);
                ffma2(a1, pack2(f1.x, f1.y), wp);
                ffma2(a2, pack2(f2.x, f2.y), wp);
                ffma2(a3, pack2(f3.x, f3.y), wp);
            }
        } else {
            #pragma unroll 4
            for (int j = s; j < tcnt; j += 2) {
                const int2 p = sm[wslot][j];
                const float wwa = fabsf(__int_as_float(p.y));
                const unsigned long long wp = pack2(wwa, wwa);
                const uint4 u = *reinterpret_cast<const uint4*>(
                    g_H16 + (size_t)p.x * D_HID + c * 8);
                const float2 f0 = __half22float2(*reinterpret_cast<const __half2*>(&u.x));
                const float2 f1 = __half22float2(*reinterpret_cast<const __half2*>(&u.y));
                const float2 f2 = __half22float2(*reinterpret_cast<const __half2*>(&u.z));
                const float2 f3 = __half22float2(*reinterpret_cast<const __half2*>(&u.w));
                ffma2(a0, pack2(f0.x, f0.y), wp);
                ffma2(a1, pack2(f1.x, f1.y), wp);
                ffma2(a2, pack2(f2.x, f2.y), wp);
                ffma2(a3, pack2(f3.x, f3.y), wp);
            }
        }
        __syncwarp();
    }

    float acc[8];
    {
        const float2 r0 = unpack2(a0), r1 = unpack2(a1);
        const float2 r2 = unpack2(a2), r3 = unpack2(a3);
        acc[0] = r0.x; acc[1] = r0.y; acc[2] = r1.x; acc[3] = r1.y;
        acc[4] = r2.x; acc[5] = r2.y; acc[6] = r3.x; acc[7] = r3.y;
    }
    #pragma unroll
    for (int k = 0; k < 8; k++)
        acc[k] += __shfl_xor_sync(0xffffffff, acc[k], 16);
    #pragma unroll
    for (int o = 16; o > 0; o >>= 1) {
        wa += __shfl_xor_sync(0xffffffff, wa, o);
        ws += __shfl_xor_sync(0xffffffff, ws, o);
    }

    // ---- per-sample epilogue ----
    auto do_sample = [&](int b, int anchor) {
        // anchor row first (independent loads overlap the LOO scan)
        const float4* Ha4 = reinterpret_cast<const float4*>(H + (size_t)anchor * D_HID);
        const float4 h0 = Ha4[2 * c];
        const float4 h1 = Ha4[2 * c + 1];

        float swa = 0.f, sws = 0.f;
        if (len <= 64) {
            #pragma unroll
            for (int k = 0; k < 2; k++) {
                const int j = lane + 32 * k;
                if (j < len) {
                    const int2 p = sm[wslot][j];
                    if (p.x == anchor) {
                        const float ww = __int_as_float(p.y);
                        sws += ww; swa += fabsf(ww);
                    }
                }
            }
        } else {
            for (int j = start + lane; j < end; j += 32) {
                if (nodes[j] == anchor) {
                    const float ww = w[j];
                    sws += ww; swa += fabsf(ww);
                }
            }
        }
        #pragma unroll
        for (int o = 16; o > 0; o >>= 1) {
            swa += __shfl_xor_sync(0xffffffff, swa, o);
            sws += __shfl_xor_sync(0xffffffff, sws, o);
        }

        const float ha[8] = { h0.x, h0.y, h0.z, h0.w, h1.x, h1.y, h1.z, h1.w };
        const float denom = fmaxf(wa - swa, 1e-12f);
        const float inv_d = 1.f / denom;
        const float sscale = (ws - sws) * inv_d;

        float v[8];
        float nv = 0.f;
        #pragma unroll
        for (int k = 0; k < 8; k++) {
            const float vk = (acc[k] - swa * ha[k]) * inv_d;
            v[k] = vk;
            nv += vk * vk;
        }
        #pragma unroll
        for (int o = 8; o > 0; o >>= 1)
            nv += __shfl_xor_sync(0xffffffff, nv, o);
        const float na = sqrtf(nv);
        const float ns = fabsf(sscale) * na;     // ||sscale * v|| exactly

        float o8[8];
        float* dst;
        if (s == 0) {
            const float inv = 1.f / fmaxf(na, 1e-6f);
            #pragma unroll
            for (int k = 0; k < 8; k++) o8[k] = v[k] * inv;
            dst = out + (size_t)b * D_HID + c * 8;
        } else {
            const float inv = (ns > 0.f) ? sscale / fmaxf(ns, 1e-6f) : sscale;
            #pragma unroll
            for (int k = 0; k < 8; k++) o8[k] = v[k] * inv;
            dst = out + (size_t)(B + b) * D_HID + c * 8;
        }
        reinterpret_cast<float4*>(dst)[0] = make_float4(o8[0], o8[1], o8[2], o8[3]);
        reinterpret_cast<float4*>(dst)[1] = make_float4(o8[4], o8[5], o8[6], o8[7]);
    };

    if (slot < CAP) {
        const int b0 = g_binfix[g * CAP + slot];
        do_sample(b0, anchor_idx[b0]);
        if (slot + 1 < cnt) {           // partner exists (slot+1 < CAP always)
            const int b1 = g_binfix[g * CAP + slot + 1];
            do_sample(b1, anchor_idx[b1]);
        }
    } else {
        // overflow sentinel: process samples of group g NOT present in the bin
        const int e = (lane < CAP) ? g_binfix[g * CAP + lane] : -1;
        for (int base = 0; base < B; base += 32) {
            const int bb = base + lane;
            const bool m = (bb < B) && (pf_gid[bb] == g);
            unsigned mask = __ballot_sync(0xffffffff, m);
            while (mask) {
                const int l = __ffs(mask) - 1;
                mask &= mask - 1;
                const int b = base + l;
                const bool inbin = __any_sync(0xffffffff, e == b);
                if (!inbin) do_sample(b, anchor_idx[b]);
            }
        }
    }
}

// ---------------------------------------------------------------------------
extern "C" void kernel_launch(void* const* d_in, const int* in_sizes, int n_in,
                              void* d_out, int out_size) {
    const float* H      = (const float*)d_in[0];   // [N, 128]
    const float* w      = (const float*)d_in[1];   // [L]
    const int*   anchor = (const int*)  d_in[2];   // [B]
    const int*   pfgid  = (const int*)  d_in[3];   // [B]
    const int*   nodes  = (const int*)  d_in[4];   // [L]
    const int*   plen   = (const int*)  d_in[5];   // [G]
    float* out = (float*)d_out;                    // [2, B, 128]

    const int B = in_sizes[2];
    const int G = in_sizes[5];
    const int n16 = in_sizes[0] / 8;               // uint4 groups of fp16 out
    const int nconv = (n16 + SCAN_T * 4 - 1) / (SCAN_T * 4);
    const int nscan = (G + SCAN_T - 1) / SCAN_T;
    const int nhist = (B + SCAN_T - 1) / SCAN_T;

    clear_kernel<<<(G / 4 + 255) / 256, 256>>>(G);
    prolog_kernel<<<nconv + nscan + nhist, SCAN_T>>>(
        (const float4*)H, n16, plen, pfgid, out, G, B, nconv, nscan);
    main_kernel<<<(B + 7) / 8, 256>>>(H, w, nodes, anchor, pfgid, out, B, G);
}